// round 2
// baseline (speedup 1.0000x reference)
#include <cuda_runtime.h>

#define NN      16384
#define EE      524288
#define IN_DIM  256
#define H1D     128
#define H2D     64

// ---------------- scratch (device globals; no allocation) ----------------
__device__ int   g_out_deg[NN];
__device__ int   g_in_deg[NN];
__device__ int   g_row_ptr[NN + 1];
__device__ int   g_write_ptr[NN];
__device__ int   g_csr_src[EE];
__device__ float g_out_norm[NN];
__device__ float g_in_norm[NN];
__device__ float g_h0[NN * H1D];   // feats @ W1
__device__ float g_h1[NN * H1D];   // relu(agg1 * in_norm + b1)
__device__ float g_z0[NN * H2D];   // h1 @ W2
__device__ float g_z [NN * H2D];   // final z (after dropout mask)

// ---------------- graph preprocessing ----------------
__global__ void k_zero_deg() {
    int i = blockIdx.x * blockDim.x + threadIdx.x;
    if (i < NN) { g_out_deg[i] = 0; g_in_deg[i] = 0; }
}

__global__ void k_count(const int* __restrict__ src, const int* __restrict__ dst) {
    int e = blockIdx.x * blockDim.x + threadIdx.x;
    if (e < EE) {
        atomicAdd(&g_out_deg[src[e]], 1);
        atomicAdd(&g_in_deg [dst[e]], 1);
    }
}

__global__ void k_norms() {
    int i = blockIdx.x * blockDim.x + threadIdx.x;
    if (i < NN) {
        float od = (float)max(g_out_deg[i], 1);
        float id = (float)max(g_in_deg [i], 1);
        g_out_norm[i] = rsqrtf(od);
        g_in_norm [i] = rsqrtf(id);
    }
}

// exclusive scan of in_deg -> row_ptr (single block, 1024 threads, 16 elems each)
__global__ void k_scan() {
    __shared__ int part[1024];
    int t = threadIdx.x;
    int base = t * 16;
    int loc[16];
    int s = 0;
#pragma unroll
    for (int i = 0; i < 16; ++i) { loc[i] = s; s += g_in_deg[base + i]; }
    part[t] = s;
    __syncthreads();
    // Hillis-Steele inclusive scan of partials
    for (int off = 1; off < 1024; off <<= 1) {
        int v = (t >= off) ? part[t - off] : 0;
        __syncthreads();
        part[t] += v;
        __syncthreads();
    }
    int pre = (t == 0) ? 0 : part[t - 1];
#pragma unroll
    for (int i = 0; i < 16; ++i) {
        int p = pre + loc[i];
        g_row_ptr[base + i]   = p;
        g_write_ptr[base + i] = p;
    }
    if (t == 1023) g_row_ptr[NN] = part[1023];
}

__global__ void k_build_csr(const int* __restrict__ src, const int* __restrict__ dst) {
    int e = blockIdx.x * blockDim.x + threadIdx.x;
    if (e < EE) {
        int p = atomicAdd(&g_write_ptr[dst[e]], 1);
        g_csr_src[p] = src[e];
    }
}

// ---------------- dense layers ----------------
// h0 = feats[N,256] @ W1[256,128].  4 rows per block, 128 threads (one per col).
__global__ void k_gemm1(const float* __restrict__ feats, const float* __restrict__ W1) {
    __shared__ float sx[4 * IN_DIM];
    int i0 = blockIdx.x * 4;
    int t = threadIdx.x;             // 0..127
    for (int idx = t; idx < 4 * IN_DIM; idx += 128)
        sx[idx] = feats[i0 * IN_DIM + idx];
    __syncthreads();
    float acc0 = 0.f, acc1 = 0.f, acc2 = 0.f, acc3 = 0.f;
#pragma unroll 8
    for (int k = 0; k < IN_DIM; ++k) {
        float w = W1[k * H1D + t];
        acc0 += sx[0 * IN_DIM + k] * w;
        acc1 += sx[1 * IN_DIM + k] * w;
        acc2 += sx[2 * IN_DIM + k] * w;
        acc3 += sx[3 * IN_DIM + k] * w;
    }
    g_h0[(i0 + 0) * H1D + t] = acc0;
    g_h0[(i0 + 1) * H1D + t] = acc1;
    g_h0[(i0 + 2) * H1D + t] = acc2;
    g_h0[(i0 + 3) * H1D + t] = acc3;
}

// agg layer 1 + epilogue: h1 = relu(agg * in_norm + b1)
__global__ void k_agg1(const float* __restrict__ b1) {
    int i = blockIdx.x;
    int f = threadIdx.x;             // 0..127
    int beg = g_row_ptr[i], end = g_row_ptr[i + 1];
    float acc = 0.f;
    for (int e = beg; e < end; ++e) {
        int s = g_csr_src[e];
        acc += g_h0[s * H1D + f] * g_out_norm[s];
    }
    float v = acc * g_in_norm[i] + b1[f];
    g_h1[i * H1D + f] = fmaxf(v, 0.f);
}

// z0 = h1[N,128] @ W2[128,64].  4 rows per block, 64 threads.
__global__ void k_gemm2(const float* __restrict__ W2) {
    __shared__ float sx[4 * H1D];
    int i0 = blockIdx.x * 4;
    int t = threadIdx.x;             // 0..63
    for (int idx = t; idx < 4 * H1D; idx += 64)
        sx[idx] = g_h1[i0 * H1D + idx];
    __syncthreads();
    float acc0 = 0.f, acc1 = 0.f, acc2 = 0.f, acc3 = 0.f;
#pragma unroll 8
    for (int k = 0; k < H1D; ++k) {
        float w = W2[k * H2D + t];
        acc0 += sx[0 * H1D + k] * w;
        acc1 += sx[1 * H1D + k] * w;
        acc2 += sx[2 * H1D + k] * w;
        acc3 += sx[3 * H1D + k] * w;
    }
    g_z0[(i0 + 0) * H2D + t] = acc0;
    g_z0[(i0 + 1) * H2D + t] = acc1;
    g_z0[(i0 + 2) * H2D + t] = acc2;
    g_z0[(i0 + 3) * H2D + t] = acc3;
}

// agg layer 2 + epilogue: z = ((agg * in_norm) + b2) * drop_mask
__global__ void k_agg2(const float* __restrict__ b2, const float* __restrict__ drop) {
    int i = blockIdx.x;
    int f = threadIdx.x;             // 0..63
    int beg = g_row_ptr[i], end = g_row_ptr[i + 1];
    float acc = 0.f;
    for (int e = beg; e < end; ++e) {
        int s = g_csr_src[e];
        acc += g_z0[s * H2D + f] * g_out_norm[s];
    }
    float v = acc * g_in_norm[i] + b2[f];
    g_z[i * H2D + f] = v * drop[i * H2D + f];
}

// ---------------- C = Z @ Z^T  (symmetric; compute upper blocks, mirror) ----------------
// 64x64 output tile per block, K = 64 (full), 256 threads, 4x4 per thread.
__global__ void __launch_bounds__(256) k_zzt(float* __restrict__ C) {
    int bj = blockIdx.x, bi = blockIdx.y;
    if (bi > bj) return;

    __shared__ float As[64][68];   // [k][row]
    __shared__ float Bs[64][68];   // [k][col]

    int tid = threadIdx.x;
    {
        int r  = tid >> 4;              // 0..15
        int kq = (tid & 15) * 4;        // 0..60
#pragma unroll
        for (int it = 0; it < 4; ++it) {
            int row = r + it * 16;
            float4 a = *(const float4*)&g_z[(bi * 64 + row) * H2D + kq];
            As[kq + 0][row] = a.x; As[kq + 1][row] = a.y;
            As[kq + 2][row] = a.z; As[kq + 3][row] = a.w;
            float4 b = *(const float4*)&g_z[(bj * 64 + row) * H2D + kq];
            Bs[kq + 0][row] = b.x; Bs[kq + 1][row] = b.y;
            Bs[kq + 2][row] = b.z; Bs[kq + 3][row] = b.w;
        }
    }
    __syncthreads();

    int tx = tid & 15, ty = tid >> 4;
    float acc[4][4] = {};
#pragma unroll 16
    for (int k = 0; k < 64; ++k) {
        float4 a = *(const float4*)&As[k][ty * 4];
        float4 b = *(const float4*)&Bs[k][tx * 4];
        acc[0][0] += a.x * b.x; acc[0][1] += a.x * b.y; acc[0][2] += a.x * b.z; acc[0][3] += a.x * b.w;
        acc[1][0] += a.y * b.x; acc[1][1] += a.y * b.y; acc[1][2] += a.y * b.z; acc[1][3] += a.y * b.w;
        acc[2][0] += a.z * b.x; acc[2][1] += a.z * b.y; acc[2][2] += a.z * b.z; acc[2][3] += a.z * b.w;
        acc[3][0] += a.w * b.x; acc[3][1] += a.w * b.y; acc[3][2] += a.w * b.z; acc[3][3] += a.w * b.w;
    }

    // direct (upper) tile write, coalesced float4
#pragma unroll
    for (int u = 0; u < 4; ++u) {
        float4 o = make_float4(acc[u][0], acc[u][1], acc[u][2], acc[u][3]);
        *(float4*)&C[(size_t)(bi * 64 + ty * 4 + u) * NN + bj * 64 + tx * 4] = o;
    }

    if (bi != bj) {
        // stage transpose in smem (reuse As) for coalesced mirrored write
        __syncthreads();
        float (*Ct)[68] = As;
#pragma unroll
        for (int u = 0; u < 4; ++u)
#pragma unroll
            for (int v = 0; v < 4; ++v)
                Ct[tx * 4 + v][ty * 4 + u] = acc[u][v];
        __syncthreads();
        int r  = tid >> 4;
        int kq = (tid & 15) * 4;
#pragma unroll
        for (int it = 0; it < 4; ++it) {
            int row = r + it * 16;  // local col index lc in transposed tile
            float4 o = *(const float4*)&Ct[row][kq];
            *(float4*)&C[(size_t)(bj * 64 + row) * NN + bi * 64 + kq] = o;
        }
    }
}

// ---------------- launch ----------------
extern "C" void kernel_launch(void* const* d_in, const int* in_sizes, int n_in,
                              void* d_out, int out_size) {
    const float* feats = (const float*)d_in[0];
    const float* W1    = (const float*)d_in[1];
    const float* b1    = (const float*)d_in[2];
    const float* W2    = (const float*)d_in[3];
    const float* b2    = (const float*)d_in[4];
    const float* drop  = (const float*)d_in[5];
    const int*   src   = (const int*)  d_in[6];
    const int*   dst   = (const int*)  d_in[7];
    float*       out   = (float*)d_out;

    k_zero_deg <<<NN / 256, 256>>>();
    k_count    <<<EE / 256, 256>>>(src, dst);
    k_norms    <<<NN / 256, 256>>>();
    k_scan     <<<1, 1024>>>();
    k_build_csr<<<EE / 256, 256>>>(src, dst);

    k_gemm1    <<<NN / 4, 128>>>(feats, W1);
    k_agg1     <<<NN, 128>>>(b1);
    k_gemm2    <<<NN / 4, 64>>>(W2);
    k_agg2     <<<NN, 64>>>(b2, drop);

    dim3 g(NN / 64, NN / 64);
    k_zzt      <<<g, 256>>>(out);
}

// round 14
// speedup vs baseline: 1.5264x; 1.5264x over previous
#include <cuda_runtime.h>
#include <cuda_bf16.h>
#include <cstdint>

#define NN      16384
#define EE      524288
#define IN_DIM  256
#define H1D     128
#define H2D     64

// ---------------- scratch (device globals; no allocation) ----------------
__device__ int   g_out_deg[NN];
__device__ int   g_in_deg[NN];
__device__ int   g_row_ptr[NN + 1];
__device__ int   g_write_ptr[NN];
__device__ int   g_csr_src[EE];
__device__ float g_out_norm[NN];
__device__ float g_in_norm[NN];
__device__ float g_h0[NN * H1D];   // feats @ W1
__device__ float g_h1[NN * H1D];   // relu(agg1 * in_norm + b1)
__device__ float g_z0[NN * H2D];   // h1 @ W2
__device__ float g_z [NN * H2D];   // final z (after dropout mask)
__device__ __nv_bfloat16 g_za[NN * H2D];  // hi(z)
__device__ __nv_bfloat16 g_zb[NN * H2D];  // lo(z) = bf16(z - hi)

// ---------------- graph preprocessing ----------------
__global__ void k_zero_deg() {
    int i = blockIdx.x * blockDim.x + threadIdx.x;
    if (i < NN) { g_out_deg[i] = 0; g_in_deg[i] = 0; }
}

__global__ void k_count(const int* __restrict__ src, const int* __restrict__ dst) {
    int e = blockIdx.x * blockDim.x + threadIdx.x;
    if (e < EE) {
        atomicAdd(&g_out_deg[src[e]], 1);
        atomicAdd(&g_in_deg [dst[e]], 1);
    }
}

__global__ void k_norms() {
    int i = blockIdx.x * blockDim.x + threadIdx.x;
    if (i < NN) {
        float od = (float)max(g_out_deg[i], 1);
        float id = (float)max(g_in_deg [i], 1);
        g_out_norm[i] = rsqrtf(od);
        g_in_norm [i] = rsqrtf(id);
    }
}

// exclusive scan of in_deg -> row_ptr (single block, 1024 threads, 16 elems each)
__global__ void k_scan() {
    __shared__ int part[1024];
    int t = threadIdx.x;
    int base = t * 16;
    int loc[16];
    int s = 0;
#pragma unroll
    for (int i = 0; i < 16; ++i) { loc[i] = s; s += g_in_deg[base + i]; }
    part[t] = s;
    __syncthreads();
    for (int off = 1; off < 1024; off <<= 1) {
        int v = (t >= off) ? part[t - off] : 0;
        __syncthreads();
        part[t] += v;
        __syncthreads();
    }
    int pre = (t == 0) ? 0 : part[t - 1];
#pragma unroll
    for (int i = 0; i < 16; ++i) {
        int p = pre + loc[i];
        g_row_ptr[base + i]   = p;
        g_write_ptr[base + i] = p;
    }
    if (t == 1023) g_row_ptr[NN] = part[1023];
}

__global__ void k_build_csr(const int* __restrict__ src, const int* __restrict__ dst) {
    int e = blockIdx.x * blockDim.x + threadIdx.x;
    if (e < EE) {
        int p = atomicAdd(&g_write_ptr[dst[e]], 1);
        g_csr_src[p] = src[e];
    }
}

// ---------------- dense layers ----------------
__global__ void k_gemm1(const float* __restrict__ feats, const float* __restrict__ W1) {
    __shared__ float sx[4 * IN_DIM];
    int i0 = blockIdx.x * 4;
    int t = threadIdx.x;
    for (int idx = t; idx < 4 * IN_DIM; idx += 128)
        sx[idx] = feats[i0 * IN_DIM + idx];
    __syncthreads();
    float acc0 = 0.f, acc1 = 0.f, acc2 = 0.f, acc3 = 0.f;
#pragma unroll 8
    for (int k = 0; k < IN_DIM; ++k) {
        float w = W1[k * H1D + t];
        acc0 += sx[0 * IN_DIM + k] * w;
        acc1 += sx[1 * IN_DIM + k] * w;
        acc2 += sx[2 * IN_DIM + k] * w;
        acc3 += sx[3 * IN_DIM + k] * w;
    }
    g_h0[(i0 + 0) * H1D + t] = acc0;
    g_h0[(i0 + 1) * H1D + t] = acc1;
    g_h0[(i0 + 2) * H1D + t] = acc2;
    g_h0[(i0 + 3) * H1D + t] = acc3;
}

__global__ void k_agg1(const float* __restrict__ b1) {
    int i = blockIdx.x;
    int f = threadIdx.x;
    int beg = g_row_ptr[i], end = g_row_ptr[i + 1];
    float acc = 0.f;
    for (int e = beg; e < end; ++e) {
        int s = g_csr_src[e];
        acc += g_h0[s * H1D + f] * g_out_norm[s];
    }
    float v = acc * g_in_norm[i] + b1[f];
    g_h1[i * H1D + f] = fmaxf(v, 0.f);
}

__global__ void k_gemm2(const float* __restrict__ W2) {
    __shared__ float sx[4 * H1D];
    int i0 = blockIdx.x * 4;
    int t = threadIdx.x;
    for (int idx = t; idx < 4 * H1D; idx += 64)
        sx[idx] = g_h1[i0 * H1D + idx];
    __syncthreads();
    float acc0 = 0.f, acc1 = 0.f, acc2 = 0.f, acc3 = 0.f;
#pragma unroll 8
    for (int k = 0; k < H1D; ++k) {
        float w = W2[k * H2D + t];
        acc0 += sx[0 * H1D + k] * w;
        acc1 += sx[1 * H1D + k] * w;
        acc2 += sx[2 * H1D + k] * w;
        acc3 += sx[3 * H1D + k] * w;
    }
    g_z0[(i0 + 0) * H2D + t] = acc0;
    g_z0[(i0 + 1) * H2D + t] = acc1;
    g_z0[(i0 + 2) * H2D + t] = acc2;
    g_z0[(i0 + 3) * H2D + t] = acc3;
}

__global__ void k_agg2(const float* __restrict__ b2, const float* __restrict__ drop) {
    int i = blockIdx.x;
    int f = threadIdx.x;
    int beg = g_row_ptr[i], end = g_row_ptr[i + 1];
    float acc = 0.f;
    for (int e = beg; e < end; ++e) {
        int s = g_csr_src[e];
        acc += g_z0[s * H2D + f] * g_out_norm[s];
    }
    float v = acc * g_in_norm[i] + b2[f];
    g_z[i * H2D + f] = v * drop[i * H2D + f];
}

// split z into bf16 hi/lo
__global__ void k_split() {
    int i = blockIdx.x * blockDim.x + threadIdx.x;
    if (i < NN * H2D) {
        float z = g_z[i];
        __nv_bfloat16 h = __float2bfloat16(z);
        float lo = z - __bfloat162float(h);
        g_za[i] = h;
        g_zb[i] = __float2bfloat16(lo);
    }
}

// ---------------- C = Z @ Z^T via bf16-split tensor cores ----------------
// CTA: 128x128 tile. 8 warps (4 m x 2 n), warp tile 32x64.
// K=64 in 2 chunks of 32; 3 term passes (hi*hi, hi*lo, lo*hi).
#define SPITCH 40   // bf16 elements per smem row (80B; conflict-free ldmatrix)

__device__ __forceinline__ void ldm_x4(uint32_t* r, uint32_t addr) {
    asm volatile("ldmatrix.sync.aligned.m8n8.x4.shared.b16 {%0,%1,%2,%3}, [%4];"
                 : "=r"(r[0]), "=r"(r[1]), "=r"(r[2]), "=r"(r[3]) : "r"(addr));
}

__device__ __forceinline__ void mma_bf16(float* d, const uint32_t* a, const uint32_t* b) {
    asm volatile("mma.sync.aligned.m16n8k16.row.col.f32.bf16.bf16.f32 "
                 "{%0,%1,%2,%3}, {%4,%5,%6,%7}, {%8,%9}, {%0,%1,%2,%3};"
                 : "+f"(d[0]), "+f"(d[1]), "+f"(d[2]), "+f"(d[3])
                 : "r"(a[0]), "r"(a[1]), "r"(a[2]), "r"(a[3]), "r"(b[0]), "r"(b[1]));
}

__global__ void __launch_bounds__(256, 2) k_zzt_tc(float* __restrict__ C) {
    __shared__ __align__(16) __nv_bfloat16 sHi[128][SPITCH];
    __shared__ __align__(16) __nv_bfloat16 sLi[128][SPITCH];
    __shared__ __align__(16) __nv_bfloat16 sHj[128][SPITCH];
    __shared__ __align__(16) __nv_bfloat16 sLj[128][SPITCH];

    const int bi = blockIdx.y, bj = blockIdx.x;
    const int tid = threadIdx.x;
    const int lane = tid & 31, wid = tid >> 5;
    const int wm = wid >> 1;         // 0..3 : warp row block (32 rows)
    const int wn = wid & 1;          // 0..1 : warp col block (64 cols)
    const int lr  = lane & 7;
    const int sel = lane >> 3;       // 0..3

    float acc[2][8][4];
#pragma unroll
    for (int a = 0; a < 2; ++a)
#pragma unroll
        for (int b = 0; b < 8; ++b)
#pragma unroll
            for (int c = 0; c < 4; ++c) acc[a][b][c] = 0.f;

    const uint32_t sbHi = (uint32_t)__cvta_generic_to_shared(&sHi[0][0]);
    const uint32_t sbLi = (uint32_t)__cvta_generic_to_shared(&sLi[0][0]);
    const uint32_t sbHj = (uint32_t)__cvta_generic_to_shared(&sHj[0][0]);
    const uint32_t sbLj = (uint32_t)__cvta_generic_to_shared(&sLj[0][0]);

    for (int ch = 0; ch < 2; ++ch) {
        // ---- stage 4 operand tiles: 128 rows x 32 bf16 each ----
#pragma unroll
        for (int half = 0; half < 2; ++half) {
            int u = tid + half * 256;      // 0..511
            int row = u >> 2;
            int part = u & 3;              // 16B chunk within 64B
            const uint4* a_src = (const uint4*)&g_za[(bi * 128 + row) * H2D + ch * 32 + part * 8];
            const uint4* b_src = (const uint4*)&g_zb[(bi * 128 + row) * H2D + ch * 32 + part * 8];
            *(uint4*)&sHi[row][part * 8] = *a_src;
            *(uint4*)&sLi[row][part * 8] = *b_src;
            const uint4* c_src = (const uint4*)&g_za[(bj * 128 + row) * H2D + ch * 32 + part * 8];
            const uint4* d_src = (const uint4*)&g_zb[(bj * 128 + row) * H2D + ch * 32 + part * 8];
            *(uint4*)&sHj[row][part * 8] = *c_src;
            *(uint4*)&sLj[row][part * 8] = *d_src;
        }
        __syncthreads();

        // ---- 3 terms: (Hi,Hj), (Hi,Lj), (Li,Hj) ----
#pragma unroll
        for (int term = 0; term < 3; ++term) {
            uint32_t sbL = (term == 2) ? sbLi : sbHi;
            uint32_t sbR = (term == 1) ? sbLj : sbHj;
#pragma unroll
            for (int ks = 0; ks < 2; ++ks) {
                const int kbase = ks * 16;
                // A fragments: 2 m-subtiles of 16x16
                uint32_t afr[2][4];
#pragma unroll
                for (int mt = 0; mt < 2; ++mt) {
                    int rowA = wm * 32 + mt * 16 + lr + (sel & 1) * 8;
                    int kbA  = kbase + (sel >> 1) * 8;
                    ldm_x4(afr[mt], sbL + (uint32_t)(rowA * (SPITCH * 2) + kbA * 2));
                }
                // B fragments: 8 n-subtiles of 8 (loaded 16n at a time)
                uint32_t bfr[8][2];
#pragma unroll
                for (int q = 0; q < 4; ++q) {
                    int rowB = wn * 64 + q * 16 + lr + (sel >> 1) * 8;
                    int kbB  = kbase + (sel & 1) * 8;
                    uint32_t r[4];
                    ldm_x4(r, sbR + (uint32_t)(rowB * (SPITCH * 2) + kbB * 2));
                    bfr[2 * q][0] = r[0]; bfr[2 * q][1] = r[1];
                    bfr[2 * q + 1][0] = r[2]; bfr[2 * q + 1][1] = r[3];
                }
#pragma unroll
                for (int mt = 0; mt < 2; ++mt)
#pragma unroll
                    for (int nt = 0; nt < 8; ++nt)
                        mma_bf16(acc[mt][nt], afr[mt], bfr[nt]);
            }
        }
        __syncthreads();
    }

    // ---- epilogue: direct coalesced-ish float2 stores ----
    const int r0 = lane >> 2;
    const int c0 = (lane & 3) * 2;
#pragma unroll
    for (int mt = 0; mt < 2; ++mt) {
#pragma unroll
        for (int nt = 0; nt < 8; ++nt) {
            size_t row = (size_t)(bi * 128 + wm * 32 + mt * 16 + r0);
            size_t col = (size_t)(bj * 128 + wn * 64 + nt * 8 + c0);
            float2 v0 = make_float2(acc[mt][nt][0], acc[mt][nt][1]);
            float2 v1 = make_float2(acc[mt][nt][2], acc[mt][nt][3]);
            *(float2*)&C[row * NN + col]       = v0;
            *(float2*)&C[(row + 8) * NN + col] = v1;
        }
    }
}

// ---------------- launch ----------------
extern "C" void kernel_launch(void* const* d_in, const int* in_sizes, int n_in,
                              void* d_out, int out_size) {
    const float* feats = (const float*)d_in[0];
    const float* W1    = (const float*)d_in[1];
    const float* b1    = (const float*)d_in[2];
    const float* W2    = (const float*)d_in[3];
    const float* b2    = (const float*)d_in[4];
    const float* drop  = (const float*)d_in[5];
    const int*   src   = (const int*)  d_in[6];
    const int*   dst   = (const int*)  d_in[7];
    float*       out   = (float*)d_out;

    k_zero_deg <<<NN / 256, 256>>>();
    k_count    <<<EE / 256, 256>>>(src, dst);
    k_norms    <<<NN / 256, 256>>>();
    k_scan     <<<1, 1024>>>();
    k_build_csr<<<EE / 256, 256>>>(src, dst);

    k_gemm1    <<<NN / 4, 128>>>(feats, W1);
    k_agg1     <<<NN, 128>>>(b1);
    k_gemm2    <<<NN / 4, 64>>>(W2);
    k_agg2     <<<NN, 64>>>(b2, drop);
    k_split    <<<NN * H2D / 256, 256>>>();

    dim3 g(NN / 128, NN / 128);
    k_zzt_tc   <<<g, 256>>>(out);
}